// round 4
// baseline (speedup 1.0000x reference)
#include <cuda_runtime.h>

#define DDIM 64
#define NREL 31
#define N_ENT_MAX 100000
#define E_MAX 1000000

// Scratch (allocation-free: __device__ globals)
__device__ float g_sq[N_ENT_MAX * NREL];   // per-(entity, relation) squared norm
__device__ float g_m[N_ENT_MAX];           // segment max
__device__ float g_s[N_ENT_MAX];           // segment sum
__device__ float g_att[E_MAX];             // per-edge att, then exp value

// ---------------------------------------------------------------------------
__global__ void k_zero_out(float* out, long long n) {
    long long i = blockIdx.x * (long long)blockDim.x + threadIdx.x;
    long long stride = (long long)gridDim.x * blockDim.x;
    for (; i < n; i += stride) out[i] = 0.0f;
}

__global__ void k_zero_ms(int n_ent) {
    int i = blockIdx.x * blockDim.x + threadIdx.x;
    if (i < n_ent) { g_m[i] = 0.0f; g_s[i] = 0.0f; }
}

// ---------------------------------------------------------------------------
// g_sq[v, r] = sum_d emb[v,d]^2 * w[r,d]^2   (warp per entity)
__global__ void k_entity_sq(const float* __restrict__ emb,
                            const float* __restrict__ weight, int n_ent) {
    __shared__ float2 w2[NREL * 32];
    for (int i = threadIdx.x; i < NREL * 32; i += blockDim.x) {
        float a = weight[2 * i], b = weight[2 * i + 1];
        w2[i] = make_float2(a * a, b * b);
    }
    __syncthreads();
    int warp = (blockIdx.x * blockDim.x + threadIdx.x) >> 5;
    int lane = threadIdx.x & 31;
    if (warp >= n_ent) return;
    float2 e = reinterpret_cast<const float2*>(emb)[warp * 32 + lane];
    float e0 = e.x * e.x, e1 = e.y * e.y;
    for (int r = 0; r < NREL; r++) {
        float2 w = w2[r * 32 + lane];
        float p = e0 * w.x + e1 * w.y;
        #pragma unroll
        for (int o = 16; o; o >>= 1) p += __shfl_xor_sync(0xffffffffu, p, o);
        if (lane == 0) g_sq[warp * NREL + r] = p;
    }
}

// ---------------------------------------------------------------------------
// Edge pass 1: att + segment max (att >= 0 so int-compare == float-compare)
__global__ void k_att(const int* __restrict__ head,
                      const int* __restrict__ tail,
                      const int* __restrict__ etype, int n_edges) {
    int e = blockIdx.x * blockDim.x + threadIdx.x;
    if (e >= n_edges) return;
    int h = head[e];
    int t = tail[e];
    int r = etype[e] - 1;
    float att = g_sq[h * NREL + r] * g_sq[t * NREL + r];
    g_att[e] = att;
    atomicMax((int*)&g_m[h], __float_as_int(att));
}

// Edge pass 2: exp + segment sum
__global__ void k_expsum(const int* __restrict__ head, int n_edges) {
    int e = blockIdx.x * blockDim.x + threadIdx.x;
    if (e >= n_edges) return;
    int h = head[e];
    float ex = __expf(g_att[e] - g_m[h]);
    g_att[e] = ex;
    atomicAdd(&g_s[h], ex);
}

// Edge pass 3: scatter  out[h] += (ex/s[h]) * emb[t] * w[r]
// 16 threads per edge, one float4 vector atomic each.
__global__ void k_scatter(const float* __restrict__ emb,
                          const float* __restrict__ weight,
                          const int* __restrict__ head,
                          const int* __restrict__ tail,
                          const int* __restrict__ etype,
                          float* __restrict__ out, int n_edges) {
    int idx = blockIdx.x * 16 + (threadIdx.x >> 4);
    int q = threadIdx.x & 15;
    if (idx >= n_edges) return;
    int h = head[idx];
    int t = tail[idx];
    int r = etype[idx] - 1;
    float w = g_att[idx] / g_s[h];
    float4 tv = reinterpret_cast<const float4*>(emb + (long long)t * DDIM)[q];
    float4 rv = reinterpret_cast<const float4*>(weight + r * DDIM)[q];
    float4 v = make_float4(w * tv.x * rv.x, w * tv.y * rv.y,
                           w * tv.z * rv.z, w * tv.w * rv.w);
    atomicAdd(reinterpret_cast<float4*>(out + (long long)h * DDIM) + q, v);
}

// ---------------------------------------------------------------------------
// COO SpMM: out_user[row] += val * emb[col]
__global__ void k_spmm(const float* __restrict__ emb,
                       const int* __restrict__ irow,
                       const int* __restrict__ icol,
                       const float* __restrict__ ival,
                       float* __restrict__ out_user, int nnz) {
    int idx = blockIdx.x * 16 + (threadIdx.x >> 4);
    int q = threadIdx.x & 15;
    if (idx >= nnz) return;
    int rr = irow[idx];
    int c  = icol[idx];
    float v = ival[idx];
    float4 ev = reinterpret_cast<const float4*>(emb + (long long)c * DDIM)[q];
    float4 av = make_float4(v * ev.x, v * ev.y, v * ev.z, v * ev.w);
    atomicAdd(reinterpret_cast<float4*>(out_user + (long long)rr * DDIM) + q, av);
}

// ---------------------------------------------------------------------------
// Per-user epilogue: score = softmax(u @ W^T); ua += (score @ W) * ua
// Warp per user; W in SMEM; everything else in shuffles.
__global__ void k_user(const float* __restrict__ user_emb,
                       const float* __restrict__ weight,
                       float* __restrict__ out_user, int n_usr) {
    __shared__ float2 sw[NREL * 32];
    for (int i = threadIdx.x; i < NREL * 32; i += blockDim.x)
        sw[i] = make_float2(weight[2 * i], weight[2 * i + 1]);
    __syncthreads();
    int u = (blockIdx.x * blockDim.x + threadIdx.x) >> 5;
    int lane = threadIdx.x & 31;
    if (u >= n_usr) return;
    float2 ue = reinterpret_cast<const float2*>(user_emb)[u * 32 + lane];
    float myLogit = 0.0f;
    for (int r = 0; r < NREL; r++) {
        float2 w = sw[r * 32 + lane];
        float p = ue.x * w.x + ue.y * w.y;
        #pragma unroll
        for (int o = 16; o; o >>= 1) p += __shfl_xor_sync(0xffffffffu, p, o);
        if (lane == r) myLogit = p;
    }
    // softmax across lanes 0..30
    float v = (lane < NREL) ? myLogit : -3.4e38f;
    float mx = v;
    #pragma unroll
    for (int o = 16; o; o >>= 1) mx = fmaxf(mx, __shfl_xor_sync(0xffffffffu, mx, o));
    float ex = (lane < NREL) ? __expf(myLogit - mx) : 0.0f;
    float sum = ex;
    #pragma unroll
    for (int o = 16; o; o >>= 1) sum += __shfl_xor_sync(0xffffffffu, sum, o);
    float score = ex / sum;
    // proj[d] = sum_r score_r * w[r,d]
    float2 pr = make_float2(0.0f, 0.0f);
    for (int r = 0; r < NREL; r++) {
        float sr = __shfl_sync(0xffffffffu, score, r);
        float2 w = sw[r * 32 + lane];
        pr.x += sr * w.x;
        pr.y += sr * w.y;
    }
    float2* uo = reinterpret_cast<float2*>(out_user) + u * 32 + lane;
    float2 ua = *uo;
    ua.x += pr.x * ua.x;
    ua.y += pr.y * ua.y;
    *uo = ua;
}

// ---------------------------------------------------------------------------
extern "C" void kernel_launch(void* const* d_in, const int* in_sizes, int n_in,
                              void* d_out, int out_size) {
    const float* entity_emb = (const float*)d_in[0];
    const float* user_emb   = (const float*)d_in[1];
    const int*   edge_index = (const int*)d_in[2];
    const int*   edge_type  = (const int*)d_in[3];
    const int*   irow       = (const int*)d_in[4];
    const int*   icol       = (const int*)d_in[5];
    const float* ival       = (const float*)d_in[6];
    const float* weight     = (const float*)d_in[7];

    int n_ent   = in_sizes[0] / DDIM;
    int n_usr   = in_sizes[1] / DDIM;
    int n_edges = in_sizes[3];
    int nnz     = in_sizes[6];

    float* out      = (float*)d_out;
    float* out_user = out + (long long)n_ent * DDIM;

    const int* head = edge_index;
    const int* tail = edge_index + n_edges;

    k_zero_out<<<2048, 256>>>(out, (long long)out_size);
    k_zero_ms<<<(n_ent + 255) / 256, 256>>>(n_ent);
    k_entity_sq<<<(n_ent * 32 + 255) / 256, 256>>>(entity_emb, weight, n_ent);
    k_att<<<(n_edges + 255) / 256, 256>>>(head, tail, edge_type, n_edges);
    k_expsum<<<(n_edges + 255) / 256, 256>>>(head, n_edges);
    k_scatter<<<(n_edges + 15) / 16, 256>>>(entity_emb, weight, head, tail,
                                            edge_type, out, n_edges);
    k_spmm<<<(nnz + 15) / 16, 256>>>(entity_emb, irow, icol, ival, out_user, nnz);
    k_user<<<(n_usr * 32 + 255) / 256, 256>>>(user_emb, weight, out_user, n_usr);
}